// round 5
// baseline (speedup 1.0000x reference)
#include <cuda_runtime.h>
#include <math.h>

#define TT   512
#define BB   128
#define DIN  102
#define HH   256
#define G4   1024
#define DLIN 128
#define KK   9

// ---------------- device scratch (no allocations allowed) ----------------
// gates layout: [dir][t][col][b]   (batch-contiguous for coalesced rnn reads)
__device__ float g_gates[(size_t)2 * TT * G4 * BB];
// h layout: [dir][slot][unit][b];  fwd: slot t+1 = h at time t (slot 0 zeros)
//                                  bwd: slot t   = h at time t (slot TT zeros)
__device__ float g_h[(size_t)2 * (TT + 1) * HH * BB];
__device__ float g_em[(size_t)BB * TT * KK];   // emissions [b][t][k]
__device__ unsigned int g_bar;

// ---------------- kernel 0: reset barrier, zero init h slots, zero out ---
__global__ void k_zero(float* out) {
    int idx = blockIdx.x * blockDim.x + threadIdx.x;
    int stride = gridDim.x * blockDim.x;
    if (idx == 0) { g_bar = 0u; out[0] = 0.f; }
    const int HB = HH * BB;  // 32768
    float* hf0 = g_h;                                             // dir0 slot 0
    float* hbT = g_h + (size_t)(TT + 1) * HB + (size_t)TT * HB;   // dir1 slot TT
    for (int i = idx; i < HB; i += stride) { hf0[i] = 0.f; hbT[i] = 0.f; }
}

// ---------------- kernel 1: gates = x @ Wih^T + b ------------------------
// grid 65536 = dir(2) x t(512) x bhalf(2) x coltile(32); 256 threads
__global__ void __launch_bounds__(256) k_proj(
    const float* __restrict__ x,
    const float* __restrict__ Wih_f, const float* __restrict__ b_f,
    const float* __restrict__ Wih_b, const float* __restrict__ b_b)
{
    unsigned bx = blockIdx.x;
    int ct  = bx & 31;
    int bh  = (bx >> 5) & 1;
    int t   = (bx >> 6) & 511;
    int dir = bx >> 15;
    const float* Wih  = dir ? Wih_b : Wih_f;
    const float* bias = dir ? b_b : b_f;
    int col0 = ct * 32;
    int tid = threadIdx.x;

    __shared__ float xs[104][68];   // x_t slice, k-major [d][b]
    __shared__ float ws[32][108];   // Wih tile [c][d]

    for (int i = tid; i < 104 * 68; i += 256) ((float*)xs)[i] = 0.f;
    for (int i = tid; i < 32 * 108; i += 256) ((float*)ws)[i] = 0.f;
    __syncthreads();

    for (int i = tid; i < 64 * DIN; i += 256) {
        int bb = i / DIN, d = i % DIN;
        xs[d][bb] = x[((size_t)(bh * 64 + bb) * TT + t) * DIN + d];
    }
    for (int i = tid; i < 32 * DIN; i += 256) {
        int c = i / DIN, d = i % DIN;
        ws[c][d] = Wih[(size_t)(col0 + c) * DIN + d];
    }
    __syncthreads();

    int lane = tid & 31, w = tid >> 5;
    int b0 = (lane & 15) * 4;
    int c0 = w * 4 + (lane >> 4) * 2;
    float acc0[4] = {0.f, 0.f, 0.f, 0.f};
    float acc1[4] = {0.f, 0.f, 0.f, 0.f};

    #pragma unroll
    for (int d = 0; d < 104; d += 4) {
        float4 w0 = *(const float4*)&ws[c0][d];
        float4 w1 = *(const float4*)&ws[c0 + 1][d];
        float wa[4] = {w0.x, w0.y, w0.z, w0.w};
        float wb[4] = {w1.x, w1.y, w1.z, w1.w};
        #pragma unroll
        for (int j = 0; j < 4; ++j) {
            float4 hv = *(const float4*)&xs[d + j][b0];
            acc0[0] += hv.x * wa[j]; acc0[1] += hv.y * wa[j];
            acc0[2] += hv.z * wa[j]; acc0[3] += hv.w * wa[j];
            acc1[0] += hv.x * wb[j]; acc1[1] += hv.y * wb[j];
            acc1[2] += hv.z * wb[j]; acc1[3] += hv.w * wb[j];
        }
    }
    float bi0 = bias[col0 + c0], bi1 = bias[col0 + c0 + 1];
    size_t base = ((size_t)dir * TT + t) * G4;
    float* out0 = g_gates + (base + col0 + c0) * BB + bh * 64 + b0;
    float* out1 = out0 + BB;
    *(float4*)out0 = make_float4(acc0[0] + bi0, acc0[1] + bi0, acc0[2] + bi0, acc0[3] + bi0);
    *(float4*)out1 = make_float4(acc1[0] + bi1, acc1[1] + bi1, acc1[2] + bi1, acc1[3] + bi1);
}

// ---------------- kernel 2: persistent BiLSTM recurrence -----------------
// 128 CTAs (64/dir), 256 threads. Each CTA owns 4 hidden units (16 gate
// rows); Whh slice + cell state stay in smem for all 512 steps.
__global__ void __launch_bounds__(256) k_rnn(
    const float* __restrict__ Whh_f, const float* __restrict__ Whh_b)
{
    int tid = threadIdx.x;
    int dir = blockIdx.x >> 6;
    int cg  = blockIdx.x & 63;
    int u0  = cg * 4;
    const float* Whh = dir ? Whh_b : Whh_f;

    __shared__ float Wsh[16][260];   // [q][k], q = gate*4 + unit
    __shared__ float hs[32][132];    // [k][b] tile of h_prev
    __shared__ float outs[128][17];  // [b][q] pre-activation gates
    __shared__ float csh[4][128];    // [u][b] persistent cell state

    for (int i = tid; i < 16 * HH; i += 256) {
        int q = i >> 8, k = i & 255;
        int row = ((q >> 2) << 8) + u0 + (q & 3);
        Wsh[q][k] = Whh[(size_t)row * HH + k];
    }
    for (int i = tid; i < 512; i += 256) ((float*)csh)[i] = 0.f;
    __syncthreads();

    int lane = tid & 31, w = tid >> 5;
    int b0 = lane * 4;
    int q0 = w * 2;
    int colA = ((q0 >> 2) << 8) + u0 + (q0 & 3);   // Whh-row index of q0

    const int HB = HH * BB;
    float* harr = g_h + (size_t)dir * (TT + 1) * HB;
    const float* gbase = g_gates + (size_t)dir * TT * G4 * BB;
    unsigned nb = gridDim.x;

    for (int s = 0; s < TT; ++s) {
        int t = dir ? (TT - 1 - s) : s;
        const float* hin  = harr + (size_t)(dir ? (t + 1) : t) * HB;
        float*       hout = harr + (size_t)(dir ? t : (t + 1)) * HB;

        float acc0[4] = {0.f, 0.f, 0.f, 0.f};
        float acc1[4] = {0.f, 0.f, 0.f, 0.f};

        for (int kt = 0; kt < 8; ++kt) {
            int k0 = kt * 32;
            const float4* src = (const float4*)(hin + (size_t)k0 * BB);
            #pragma unroll
            for (int i = 0; i < 4; ++i) {
                int f = tid + 256 * i;
                int row = f >> 5, cq = f & 31;
                *(float4*)&hs[row][cq * 4] = src[row * 32 + cq];
            }
            __syncthreads();
            #pragma unroll
            for (int kk = 0; kk < 32; kk += 4) {
                float4 w0 = *(const float4*)&Wsh[q0][k0 + kk];
                float4 w1 = *(const float4*)&Wsh[q0 + 1][k0 + kk];
                float wa[4] = {w0.x, w0.y, w0.z, w0.w};
                float wb[4] = {w1.x, w1.y, w1.z, w1.w};
                #pragma unroll
                for (int j = 0; j < 4; ++j) {
                    float4 hv = *(const float4*)&hs[kk + j][b0];
                    acc0[0] += hv.x * wa[j]; acc0[1] += hv.y * wa[j];
                    acc0[2] += hv.z * wa[j]; acc0[3] += hv.w * wa[j];
                    acc1[0] += hv.x * wb[j]; acc1[1] += hv.y * wb[j];
                    acc1[2] += hv.z * wb[j]; acc1[3] += hv.w * wb[j];
                }
            }
            __syncthreads();
        }

        // add precomputed input-projection gates, stage to shared
        const float* gt = gbase + (size_t)t * G4 * BB;
        {
            float4 ga = ((const float4*)(gt + (size_t)colA * BB))[lane];
            float4 gb = ((const float4*)(gt + (size_t)(colA + 1) * BB))[lane];
            outs[b0 + 0][q0] = acc0[0] + ga.x;
            outs[b0 + 1][q0] = acc0[1] + ga.y;
            outs[b0 + 2][q0] = acc0[2] + ga.z;
            outs[b0 + 3][q0] = acc0[3] + ga.w;
            outs[b0 + 0][q0 + 1] = acc1[0] + gb.x;
            outs[b0 + 1][q0 + 1] = acc1[1] + gb.y;
            outs[b0 + 2][q0 + 1] = acc1[2] + gb.z;
            outs[b0 + 3][q0 + 1] = acc1[3] + gb.w;
        }
        __syncthreads();

        // LSTM cell epilogue: 512 (b,u) pairs
        #pragma unroll
        for (int rep = 0; rep < 2; ++rep) {
            int p = tid + rep * 256;
            int b = p & 127, u = p >> 7;
            float iv = outs[b][u];
            float fv = outs[b][4 + u];
            float gv = outs[b][8 + u];
            float ov = outs[b][12 + u];
            iv = 1.f / (1.f + expf(-iv));
            fv = 1.f / (1.f + expf(-fv));
            gv = tanhf(gv);
            ov = 1.f / (1.f + expf(-ov));
            float c = fv * csh[u][b] + iv * gv;
            csh[u][b] = c;
            hout[(size_t)(u0 + u) * BB + b] = ov * tanhf(c);
        }

        __threadfence();
        __syncthreads();
        if (tid == 0) {
            atomicAdd(&g_bar, 1u);
            unsigned target = (unsigned)(s + 1) * nb;
            while (*((volatile unsigned int*)&g_bar) < target) {}
        }
        __syncthreads();
        __threadfence();
    }
}

// ---------------- kernel 3: feats = elu(hcat@Wlin^T+blin); em = feats@Wcls^T+bcls
// grid 1024 = t(512) x bhalf(2); 256 threads; 64 b x 128 n, Kdim=512
__global__ void __launch_bounds__(256) k_feats(
    const float* __restrict__ Wlin, const float* __restrict__ blin,
    const float* __restrict__ Wcls, const float* __restrict__ bcls)
{
    unsigned bx = blockIdx.x;
    int bh = bx & 1;
    int t  = bx >> 1;
    int tid = threadIdx.x;

    __shared__ float smem[9616];
    float* As = smem;               // [32][68]  k-slab x 64 b
    float* Ws = smem + 2176;        // [128][36] n x k-slab
    float* Fs = smem;               // phase2: [64][132] feats
    float* Wc = smem + 8448;        // [9][128]
    float* bc = smem + 9600;        // [9]

    // classifier weights (region disjoint from As/Ws and Fs)
    for (int i = tid; i < KK * DLIN; i += 256) Wc[i] = Wcls[i];
    if (tid < KK) bc[tid] = bcls[tid];

    int lane = tid & 31, w = tid >> 5;
    int b0 = (lane & 15) * 4;
    int n0 = w * 16 + (lane >> 4) * 8;
    float acc[8][4];
    #pragma unroll
    for (int n = 0; n < 8; ++n)
        #pragma unroll
        for (int c = 0; c < 4; ++c) acc[n][c] = 0.f;

    const int HB = HH * BB;
    const float* hf = g_h + (size_t)(t + 1) * HB;                         // fwd h_t
    const float* hb = g_h + (size_t)(TT + 1) * HB + (size_t)t * HB;       // bwd h_t

    for (int kc = 0; kc < 16; ++kc) {
        __syncthreads();
        int kbase = kc * 32;
        for (int i = tid; i < 32 * 64; i += 256) {
            int kr = i >> 6, bb = i & 63;
            int k = kbase + kr;
            float v = (k < HH) ? hf[(size_t)k * BB + bh * 64 + bb]
                               : hb[(size_t)(k - HH) * BB + bh * 64 + bb];
            As[kr * 68 + bb] = v;
        }
        for (int i = tid; i < 128 * 32; i += 256) {
            int n = i >> 5, kr = i & 31;
            Ws[n * 36 + kr] = Wlin[(size_t)n * 512 + kbase + kr];
        }
        __syncthreads();
        #pragma unroll 4
        for (int kr = 0; kr < 32; ++kr) {
            float4 hv = *(const float4*)&As[kr * 68 + b0];
            #pragma unroll
            for (int n = 0; n < 8; ++n) {
                float wv = Ws[(n0 + n) * 36 + kr];
                acc[n][0] += hv.x * wv;
                acc[n][1] += hv.y * wv;
                acc[n][2] += hv.z * wv;
                acc[n][3] += hv.w * wv;
            }
        }
    }
    __syncthreads();

    // ELU + store feats to shared
    #pragma unroll
    for (int n = 0; n < 8; ++n) {
        float bl = blin[n0 + n];
        #pragma unroll
        for (int c = 0; c < 4; ++c) {
            float v = acc[n][c] + bl;
            v = (v > 0.f) ? v : expm1f(v);
            Fs[(b0 + c) * 132 + n0 + n] = v;
        }
    }
    __syncthreads();

    // emissions: 64 b x 9 k
    for (int p = tid; p < 64 * KK; p += 256) {
        int b = p / KK, k9 = p % KK;
        const float4* fr = (const float4*)&Fs[b * 132];
        const float4* wr = (const float4*)&Wc[k9 * 128];
        float s = 0.f;
        #pragma unroll
        for (int i = 0; i < 32; ++i) {
            float4 f = fr[i], ww = wr[i];
            s += f.x * ww.x + f.y * ww.y + f.z * ww.z + f.w * ww.w;
        }
        int bg = bh * 64 + b;
        g_em[((size_t)bg * TT + t) * KK + k9] = s + bc[k9];
    }
}

// ---------------- kernel 4: CRF NLL --------------------------------------
// one warp per batch element; alpha[9] across lanes, shfl-based logsumexp
__global__ void k_crf(const int* __restrict__ labels,
                      const float* __restrict__ start_t,
                      const float* __restrict__ end_t,
                      const float* __restrict__ trans,
                      float* out)
{
    int b = blockIdx.x;
    int j = threadIdx.x;                 // 0..31
    const float* em = g_em + (size_t)b * TT * KK;
    int jj = (j < KK) ? j : 0;
    float tr[KK];
    #pragma unroll
    for (int i = 0; i < KK; ++i) tr[i] = trans[i * KK + jj];

    float alpha = (j < KK) ? (start_t[j] + em[j]) : -1e30f;
    for (int t = 1; t < TT; ++t) {
        float e = (j < KK) ? em[t * KK + j] : 0.f;
        float v[KK];
        float m = -1e30f;
        #pragma unroll
        for (int i = 0; i < KK; ++i) {
            float ai = __shfl_sync(0xffffffffu, alpha, i);
            v[i] = ai + tr[i];
            m = fmaxf(m, v[i]);
        }
        float s = 0.f;
        #pragma unroll
        for (int i = 0; i < KK; ++i) s += expf(v[i] - m);
        float na = m + logf(s) + e;
        alpha = (j < KK) ? na : -1e30f;
    }
    // logZ = logsumexp_j(alpha_j + end_t[j])
    float z = (j < KK) ? (alpha + end_t[j]) : -1e30f;
    float m = z;
    #pragma unroll
    for (int o = 16; o > 0; o >>= 1) m = fmaxf(m, __shfl_xor_sync(0xffffffffu, m, o));
    float s = (j < KK) ? expf(z - m) : 0.f;
    #pragma unroll
    for (int o = 16; o > 0; o >>= 1) s += __shfl_xor_sync(0xffffffffu, s, o);
    float logZ = m + logf(s);

    // numerator (mask is all-ones for this dataset)
    const int* lb = labels + (size_t)b * TT;
    float part = 0.f;
    for (int t = 1 + j; t < TT; t += 32) {
        int lp = lb[t - 1], lc = lb[t];
        part += trans[lp * KK + lc] + em[t * KK + lc];
    }
    #pragma unroll
    for (int o = 16; o > 0; o >>= 1) part += __shfl_xor_sync(0xffffffffu, part, o);

    if (j == 0) {
        int l0 = lb[0];
        float num = part + start_t[l0] + em[l0] + end_t[lb[TT - 1]];
        atomicAdd(out, logZ - num);
    }
}

// ---------------- host launcher ------------------------------------------
extern "C" void kernel_launch(void* const* d_in, const int* in_sizes, int n_in,
                              void* d_out, int out_size) {
    const float* x      = (const float*)d_in[0];
    // d_in[1] = seq_len (unused: all T), d_in[3] = mask (unused: all ones)
    const int*   labels = (const int*)d_in[2];
    const float* Wih_f  = (const float*)d_in[4];
    const float* Whh_f  = (const float*)d_in[5];
    const float* b_f    = (const float*)d_in[6];
    const float* Wih_b  = (const float*)d_in[7];
    const float* Whh_b  = (const float*)d_in[8];
    const float* b_b    = (const float*)d_in[9];
    const float* Wlin   = (const float*)d_in[10];
    const float* blin   = (const float*)d_in[11];
    const float* Wcls   = (const float*)d_in[12];
    const float* bcls   = (const float*)d_in[13];
    const float* start_t= (const float*)d_in[14];
    const float* end_t  = (const float*)d_in[15];
    const float* trans  = (const float*)d_in[16];
    float* out = (float*)d_out;

    k_zero<<<64, 256>>>(out);
    k_proj<<<65536, 256>>>(x, Wih_f, b_f, Wih_b, b_b);
    k_rnn<<<128, 256>>>(Whh_f, Whh_b);
    k_feats<<<1024, 256>>>(Wlin, blin, Wcls, bcls);
    k_crf<<<128, 32>>>(labels, start_t, end_t, trans, out);
}

// round 6
// speedup vs baseline: 1.3945x; 1.3945x over previous
#include <cuda_runtime.h>
#include <math.h>

#define TT   512
#define BB   128
#define DIN  102
#define HH   256
#define G4   1024
#define DLIN 128
#define KK   9

// ---------------- device scratch ----------------
// gates layout: [dir][t][col][b]
__device__ float g_gates[(size_t)2 * TT * G4 * BB];
// h layout: [dir][slot][unit][b]; fwd: slot t+1 = h(t), slot0 zeros
//                                 bwd: slot t   = h(t), slot TT zeros
__device__ float g_h[(size_t)2 * (TT + 1) * HH * BB];
__device__ float g_em[(size_t)BB * TT * KK];
__device__ unsigned int g_bar2[2];

__device__ __forceinline__ float d2t(float x) {   // round-to-nearest tf32
    float r;
    asm("cvt.rna.tf32.f32 %0, %1;" : "=f"(r) : "f"(x));
    return r;
}
__device__ __forceinline__ void mma8(float* d, const float* a, float b0, float b1) {
    asm volatile(
        "mma.sync.aligned.m16n8k8.row.col.f32.tf32.tf32.f32 "
        "{%0,%1,%2,%3}, {%4,%5,%6,%7}, {%8,%9}, {%0,%1,%2,%3};\n"
        : "+f"(d[0]), "+f"(d[1]), "+f"(d[2]), "+f"(d[3])
        : "r"(__float_as_uint(a[0])), "r"(__float_as_uint(a[1])),
          "r"(__float_as_uint(a[2])), "r"(__float_as_uint(a[3])),
          "r"(__float_as_uint(b0)), "r"(__float_as_uint(b1)));
}
__device__ __forceinline__ float sigf(float x)  { return 1.f / (1.f + __expf(-x)); }
__device__ __forceinline__ float tanhfx(float x){ return 2.f / (1.f + __expf(-2.f * x)) - 1.f; }

// ---------------- kernel 0 ----------------
__global__ void k_zero(float* out) {
    int idx = blockIdx.x * blockDim.x + threadIdx.x;
    int stride = gridDim.x * blockDim.x;
    if (idx == 0) { g_bar2[0] = 0u; g_bar2[1] = 0u; out[0] = 0.f; }
    const int HB = HH * BB;
    float* hf0 = g_h;
    float* hbT = g_h + (size_t)(TT + 1) * HB + (size_t)TT * HB;
    for (int i = idx; i < HB; i += stride) { hf0[i] = 0.f; hbT[i] = 0.f; }
}

// ---------------- kernel 1: gates = x @ Wih^T + b (unchanged) -----------
__global__ void __launch_bounds__(256) k_proj(
    const float* __restrict__ x,
    const float* __restrict__ Wih_f, const float* __restrict__ b_f,
    const float* __restrict__ Wih_b, const float* __restrict__ b_b)
{
    unsigned bx = blockIdx.x;
    int ct  = bx & 31;
    int bh  = (bx >> 5) & 1;
    int t   = (bx >> 6) & 511;
    int dir = bx >> 15;
    const float* Wih  = dir ? Wih_b : Wih_f;
    const float* bias = dir ? b_b : b_f;
    int col0 = ct * 32;
    int tid = threadIdx.x;

    __shared__ float xs[104][68];
    __shared__ float ws[32][108];

    for (int i = tid; i < 104 * 68; i += 256) ((float*)xs)[i] = 0.f;
    for (int i = tid; i < 32 * 108; i += 256) ((float*)ws)[i] = 0.f;
    __syncthreads();

    for (int i = tid; i < 64 * DIN; i += 256) {
        int bb = i / DIN, d = i % DIN;
        xs[d][bb] = x[((size_t)(bh * 64 + bb) * TT + t) * DIN + d];
    }
    for (int i = tid; i < 32 * DIN; i += 256) {
        int c = i / DIN, d = i % DIN;
        ws[c][d] = Wih[(size_t)(col0 + c) * DIN + d];
    }
    __syncthreads();

    int lane = tid & 31, w = tid >> 5;
    int b0 = (lane & 15) * 4;
    int c0 = w * 4 + (lane >> 4) * 2;
    float acc0[4] = {0.f, 0.f, 0.f, 0.f};
    float acc1[4] = {0.f, 0.f, 0.f, 0.f};

    #pragma unroll
    for (int d = 0; d < 104; d += 4) {
        float4 w0 = *(const float4*)&ws[c0][d];
        float4 w1 = *(const float4*)&ws[c0 + 1][d];
        float wa[4] = {w0.x, w0.y, w0.z, w0.w};
        float wb[4] = {w1.x, w1.y, w1.z, w1.w};
        #pragma unroll
        for (int j = 0; j < 4; ++j) {
            float4 hv = *(const float4*)&xs[d + j][b0];
            acc0[0] += hv.x * wa[j]; acc0[1] += hv.y * wa[j];
            acc0[2] += hv.z * wa[j]; acc0[3] += hv.w * wa[j];
            acc1[0] += hv.x * wb[j]; acc1[1] += hv.y * wb[j];
            acc1[2] += hv.z * wb[j]; acc1[3] += hv.w * wb[j];
        }
    }
    float bi0 = bias[col0 + c0], bi1 = bias[col0 + c0 + 1];
    size_t base = ((size_t)dir * TT + t) * G4;
    float* out0 = g_gates + (base + col0 + c0) * BB + bh * 64 + b0;
    float* out1 = out0 + BB;
    *(float4*)out0 = make_float4(acc0[0] + bi0, acc0[1] + bi0, acc0[2] + bi0, acc0[3] + bi0);
    *(float4*)out1 = make_float4(acc1[0] + bi1, acc1[1] + bi1, acc1[2] + bi1, acc1[3] + bi1);
}

// ---------------- kernel 2: persistent BiLSTM, tf32 mma.sync -------------
// 128 CTAs (64/dir), 256 thr. CTA owns 16 gate rows (4 units); the Whh
// slice lives entirely in per-warp A-fragment REGISTERS for all 512 steps.
__global__ void __launch_bounds__(256, 1) k_rnn(
    const float* __restrict__ Whh_f, const float* __restrict__ Whh_b)
{
    int tid  = threadIdx.x;
    int lane = tid & 31, w = tid >> 5;
    int dir  = blockIdx.x >> 6;
    int cg   = blockIdx.x & 63;
    int u0   = cg * 4;
    const float* Whh = dir ? Whh_b : Whh_f;

    __shared__ float hs[32][136];    // h_prev k-tile [k][b], padded: conflict-free frags
    __shared__ float csh[4][128];    // persistent cell state [u][b]

    int q  = lane >> 2;              // 0..7  (fragment group)
    int tg = lane & 3;               // 0..3
    int rowA = ((q >> 2) << 8) + u0 + (q & 3);           // mma row q
    int q2 = q + 8;
    int rowB = ((q2 >> 2) << 8) + u0 + (q2 & 3);         // mma row q+8

    // A fragments: whole Whh slice in registers (tf32-rounded)
    float aF[32][4];
    #pragma unroll
    for (int kk = 0; kk < 32; ++kk) {
        int k0 = kk * 8;
        aF[kk][0] = d2t(Whh[(size_t)rowA * HH + k0 + tg]);
        aF[kk][1] = d2t(Whh[(size_t)rowB * HH + k0 + tg]);
        aF[kk][2] = d2t(Whh[(size_t)rowA * HH + k0 + tg + 4]);
        aF[kk][3] = d2t(Whh[(size_t)rowB * HH + k0 + tg + 4]);
    }
    for (int i = tid; i < 512; i += 256) ((float*)csh)[i] = 0.f;
    __syncthreads();

    const int HB = HH * BB;
    float* harr = g_h + (size_t)dir * (TT + 1) * HB;
    const float* gbase = g_gates + (size_t)dir * TT * (size_t)G4 * BB;
    int n0 = w * 16;                 // this warp's 16 batch columns
    int cbase = n0 + 2 * tg;

    for (int s = 0; s < TT; ++s) {
        int t = dir ? (TT - 1 - s) : s;
        const float* hin  = harr + (size_t)(dir ? (t + 1) : t) * HB;
        float*       hout = harr + (size_t)(dir ? t : (t + 1)) * HB;

        float acc[2][4] = {{0.f,0.f,0.f,0.f},{0.f,0.f,0.f,0.f}};

        #pragma unroll
        for (int kt = 0; kt < 8; ++kt) {
            const float4* src = (const float4*)(hin + (size_t)kt * 32 * BB);
            float4 v[4];
            #pragma unroll
            for (int i = 0; i < 4; ++i) v[i] = src[tid + 256 * i];
            __syncthreads();
            #pragma unroll
            for (int i = 0; i < 4; ++i) {
                int f = tid + 256 * i;
                int row = f >> 5, cq = f & 31;
                hs[row][cq * 4 + 0] = d2t(v[i].x);
                hs[row][cq * 4 + 1] = d2t(v[i].y);
                hs[row][cq * 4 + 2] = d2t(v[i].z);
                hs[row][cq * 4 + 3] = d2t(v[i].w);
            }
            __syncthreads();
            #pragma unroll
            for (int k2 = 0; k2 < 4; ++k2) {
                int kk = kt * 4 + k2;
                int kb = k2 * 8;
                #pragma unroll
                for (int nt = 0; nt < 2; ++nt) {
                    float b0 = hs[kb + tg][n0 + nt * 8 + q];
                    float b1 = hs[kb + tg + 4][n0 + nt * 8 + q];
                    mma8(acc[nt], aF[kk], b0, b1);
                }
            }
        }

        // add input-projection gates (exact fp32)
        const float* gt = gbase + (size_t)t * (G4 * BB);
        #pragma unroll
        for (int nt = 0; nt < 2; ++nt) {
            float2 ga = *(const float2*)&gt[(size_t)rowA * BB + cbase + nt * 8];
            float2 gb = *(const float2*)&gt[(size_t)rowB * BB + cbase + nt * 8];
            acc[nt][0] += ga.x; acc[nt][1] += ga.y;
            acc[nt][2] += gb.x; acc[nt][3] += gb.y;
        }

        // exchange halves: lane<16 holds (i,g), lane>=16 holds (f,o), same unit/cols
        float p[2][4];
        #pragma unroll
        for (int nt = 0; nt < 2; ++nt)
            #pragma unroll
            for (int j = 0; j < 4; ++j)
                p[nt][j] = __shfl_xor_sync(0xffffffffu, acc[nt][j], 16);

        int half = lane >> 4;        // which n-tile this lane finalizes
        int u = q & 3;
        int bcol = cbase + half * 8;
        float iv0, iv1, gv0, gv1, fv0, fv1, ov0, ov1;
        if (half == 0) {
            iv0 = acc[0][0]; iv1 = acc[0][1]; gv0 = acc[0][2]; gv1 = acc[0][3];
            fv0 = p[0][0];   fv1 = p[0][1];   ov0 = p[0][2];   ov1 = p[0][3];
        } else {
            fv0 = acc[1][0]; fv1 = acc[1][1]; ov0 = acc[1][2]; ov1 = acc[1][3];
            iv0 = p[1][0];   iv1 = p[1][1];   gv0 = p[1][2];   gv1 = p[1][3];
        }
        float c0 = csh[u][bcol], c1 = csh[u][bcol + 1];
        c0 = sigf(fv0) * c0 + sigf(iv0) * tanhfx(gv0);
        c1 = sigf(fv1) * c1 + sigf(iv1) * tanhfx(gv1);
        csh[u][bcol] = c0; csh[u][bcol + 1] = c1;
        float h0 = sigf(ov0) * tanhfx(c0);
        float h1 = sigf(ov1) * tanhfx(c1);
        *(float2*)&hout[(size_t)(u0 + u) * BB + bcol] = make_float2(h0, h1);

        // per-direction grid barrier
        __threadfence();
        __syncthreads();
        if (tid == 0) {
            atomicAdd(&g_bar2[dir], 1u);
            unsigned target = (unsigned)(s + 1) * 64u;
            while (*((volatile unsigned int*)&g_bar2[dir]) < target) {}
        }
        __syncthreads();
        __threadfence();
    }
}

// ---------------- kernel 3: feats + emissions (unchanged) ----------------
__global__ void __launch_bounds__(256) k_feats(
    const float* __restrict__ Wlin, const float* __restrict__ blin,
    const float* __restrict__ Wcls, const float* __restrict__ bcls)
{
    unsigned bx = blockIdx.x;
    int bh = bx & 1;
    int t  = bx >> 1;
    int tid = threadIdx.x;

    __shared__ float smem[9616];
    float* As = smem;               // [32][68]
    float* Ws = smem + 2176;        // [128][36]
    float* Fs = smem;               // phase2: [64][132]
    float* Wc = smem + 8448;        // [9][128]
    float* bc = smem + 9600;        // [9]

    for (int i = tid; i < KK * DLIN; i += 256) Wc[i] = Wcls[i];
    if (tid < KK) bc[tid] = bcls[tid];

    int lane = tid & 31, w = tid >> 5;
    int b0 = (lane & 15) * 4;
    int n0 = w * 16 + (lane >> 4) * 8;
    float acc[8][4];
    #pragma unroll
    for (int n = 0; n < 8; ++n)
        #pragma unroll
        for (int c = 0; c < 4; ++c) acc[n][c] = 0.f;

    const int HB = HH * BB;
    const float* hf = g_h + (size_t)(t + 1) * HB;
    const float* hb = g_h + (size_t)(TT + 1) * HB + (size_t)t * HB;

    for (int kc = 0; kc < 16; ++kc) {
        __syncthreads();
        int kbase = kc * 32;
        for (int i = tid; i < 32 * 64; i += 256) {
            int kr = i >> 6, bb = i & 63;
            int k = kbase + kr;
            float v = (k < HH) ? hf[(size_t)k * BB + bh * 64 + bb]
                               : hb[(size_t)(k - HH) * BB + bh * 64 + bb];
            As[kr * 68 + bb] = v;
        }
        for (int i = tid; i < 128 * 32; i += 256) {
            int n = i >> 5, kr = i & 31;
            Ws[n * 36 + kr] = Wlin[(size_t)n * 512 + kbase + kr];
        }
        __syncthreads();
        #pragma unroll 4
        for (int kr = 0; kr < 32; ++kr) {
            float4 hv = *(const float4*)&As[kr * 68 + b0];
            #pragma unroll
            for (int n = 0; n < 8; ++n) {
                float wv = Ws[(n0 + n) * 36 + kr];
                acc[n][0] += hv.x * wv;
                acc[n][1] += hv.y * wv;
                acc[n][2] += hv.z * wv;
                acc[n][3] += hv.w * wv;
            }
        }
    }
    __syncthreads();

    #pragma unroll
    for (int n = 0; n < 8; ++n) {
        float bl = blin[n0 + n];
        #pragma unroll
        for (int c = 0; c < 4; ++c) {
            float v = acc[n][c] + bl;
            v = (v > 0.f) ? v : expm1f(v);
            Fs[(b0 + c) * 132 + n0 + n] = v;
        }
    }
    __syncthreads();

    for (int p = tid; p < 64 * KK; p += 256) {
        int b = p / KK, k9 = p % KK;
        const float4* fr = (const float4*)&Fs[b * 132];
        const float4* wr = (const float4*)&Wc[k9 * 128];
        float s = 0.f;
        #pragma unroll
        for (int i = 0; i < 32; ++i) {
            float4 f = fr[i], ww = wr[i];
            s += f.x * ww.x + f.y * ww.y + f.z * ww.z + f.w * ww.w;
        }
        int bg = bh * 64 + b;
        g_em[((size_t)bg * TT + t) * KK + k9] = s + bc[k9];
    }
}

// ---------------- kernel 4: CRF NLL (unchanged) --------------------------
__global__ void k_crf(const int* __restrict__ labels,
                      const float* __restrict__ start_t,
                      const float* __restrict__ end_t,
                      const float* __restrict__ trans,
                      float* out)
{
    int b = blockIdx.x;
    int j = threadIdx.x;
    const float* em = g_em + (size_t)b * TT * KK;
    int jj = (j < KK) ? j : 0;
    float tr[KK];
    #pragma unroll
    for (int i = 0; i < KK; ++i) tr[i] = trans[i * KK + jj];

    float alpha = (j < KK) ? (start_t[j] + em[j]) : -1e30f;
    for (int t = 1; t < TT; ++t) {
        float e = (j < KK) ? em[t * KK + j] : 0.f;
        float v[KK];
        float m = -1e30f;
        #pragma unroll
        for (int i = 0; i < KK; ++i) {
            float ai = __shfl_sync(0xffffffffu, alpha, i);
            v[i] = ai + tr[i];
            m = fmaxf(m, v[i]);
        }
        float s = 0.f;
        #pragma unroll
        for (int i = 0; i < KK; ++i) s += expf(v[i] - m);
        float na = m + logf(s) + e;
        alpha = (j < KK) ? na : -1e30f;
    }
    float z = (j < KK) ? (alpha + end_t[j]) : -1e30f;
    float m = z;
    #pragma unroll
    for (int o = 16; o > 0; o >>= 1) m = fmaxf(m, __shfl_xor_sync(0xffffffffu, m, o));
    float s = (j < KK) ? expf(z - m) : 0.f;
    #pragma unroll
    for (int o = 16; o > 0; o >>= 1) s += __shfl_xor_sync(0xffffffffu, s, o);
    float logZ = m + logf(s);

    const int* lb = labels + (size_t)b * TT;
    float part = 0.f;
    for (int t = 1 + j; t < TT; t += 32) {
        int lp = lb[t - 1], lc = lb[t];
        part += trans[lp * KK + lc] + em[t * KK + lc];
    }
    #pragma unroll
    for (int o = 16; o > 0; o >>= 1) part += __shfl_xor_sync(0xffffffffu, part, o);

    if (j == 0) {
        int l0 = lb[0];
        float num = part + start_t[l0] + em[l0] + end_t[lb[TT - 1]];
        atomicAdd(out, logZ - num);
    }
}

// ---------------- host launcher ------------------------------------------
extern "C" void kernel_launch(void* const* d_in, const int* in_sizes, int n_in,
                              void* d_out, int out_size) {
    const float* x      = (const float*)d_in[0];
    const int*   labels = (const int*)d_in[2];
    const float* Wih_f  = (const float*)d_in[4];
    const float* Whh_f  = (const float*)d_in[5];
    const float* b_f    = (const float*)d_in[6];
    const float* Wih_b  = (const float*)d_in[7];
    const float* Whh_b  = (const float*)d_in[8];
    const float* b_b    = (const float*)d_in[9];
    const float* Wlin   = (const float*)d_in[10];
    const float* blin   = (const float*)d_in[11];
    const float* Wcls   = (const float*)d_in[12];
    const float* bcls   = (const float*)d_in[13];
    const float* start_t= (const float*)d_in[14];
    const float* end_t  = (const float*)d_in[15];
    const float* trans  = (const float*)d_in[16];
    float* out = (float*)d_out;

    k_zero<<<64, 256>>>(out);
    k_proj<<<65536, 256>>>(x, Wih_f, b_f, Wih_b, b_b);
    k_rnn<<<128, 256>>>(Whh_f, Whh_b);
    k_feats<<<1024, 256>>>(Wlin, blin, Wcls, bcls);
    k_crf<<<128, 32>>>(labels, start_t, end_t, trans, out);
}

// round 8
// speedup vs baseline: 2.4729x; 1.7733x over previous
#include <cuda_runtime.h>
#include <math.h>

#define TT   512
#define BB   128
#define DIN  102
#define HH   256
#define G4   1024
#define DLIN 128
#define KK   9

// ---------------- device scratch ----------------
// gates layout: [dir][t][col][b]
__device__ float g_gates[(size_t)2 * TT * G4 * BB];
// h layout: [dir][slot][unit][b]; fwd: slot t+1 = h(t), slot0 zeros
//                                 bwd: slot t   = h(t), slot TT zeros
__device__ float g_h[(size_t)2 * (TT + 1) * HH * BB];
__device__ float g_em[(size_t)BB * TT * KK];
__device__ unsigned int g_bar4[4];

__device__ __forceinline__ float d2t(float x) {   // round-to-nearest tf32
    float r;
    asm("cvt.rna.tf32.f32 %0, %1;" : "=f"(r) : "f"(x));
    return r;
}
__device__ __forceinline__ void mma8(float* d, const float* a, float b0, float b1) {
    asm volatile(
        "mma.sync.aligned.m16n8k8.row.col.f32.tf32.tf32.f32 "
        "{%0,%1,%2,%3}, {%4,%5,%6,%7}, {%8,%9}, {%0,%1,%2,%3};\n"
        : "+f"(d[0]), "+f"(d[1]), "+f"(d[2]), "+f"(d[3])
        : "r"(__float_as_uint(a[0])), "r"(__float_as_uint(a[1])),
          "r"(__float_as_uint(a[2])), "r"(__float_as_uint(a[3])),
          "r"(__float_as_uint(b0)), "r"(__float_as_uint(b1)));
}
__device__ __forceinline__ float sigf(float x)  { return 1.f / (1.f + __expf(-x)); }
__device__ __forceinline__ float tanhfx(float x){ return 2.f / (1.f + __expf(-2.f * x)) - 1.f; }

// ---------------- kernel 0 ----------------
__global__ void k_zero(float* out) {
    int idx = blockIdx.x * blockDim.x + threadIdx.x;
    int stride = gridDim.x * blockDim.x;
    if (idx == 0) {
        g_bar4[0] = 0u; g_bar4[1] = 0u; g_bar4[2] = 0u; g_bar4[3] = 0u;
        out[0] = 0.f;
    }
    const int HB = HH * BB;
    float* hf0 = g_h;
    float* hbT = g_h + (size_t)(TT + 1) * HB + (size_t)TT * HB;
    for (int i = idx; i < HB; i += stride) { hf0[i] = 0.f; hbT[i] = 0.f; }
}

// ---------------- kernel 1: gates = x @ Wih^T + b  (tf32 mma) ------------
// grid 16384 = dir(2) x t(512) x colt(8) x bh(2); 256 threads
// CTA tile: 128 gate cols x 64 batch, K=104 (padded from 102)
__global__ void __launch_bounds__(256) k_proj(
    const float* __restrict__ x,
    const float* __restrict__ Wih_f, const float* __restrict__ b_f,
    const float* __restrict__ Wih_b, const float* __restrict__ b_b)
{
    unsigned bx = blockIdx.x;
    int bh   = bx & 1;
    int colt = (bx >> 1) & 7;
    int t    = (bx >> 4) & 511;
    int dir  = bx >> 13;
    const float* Wih  = dir ? Wih_b : Wih_f;
    const float* bias = dir ? b_b : b_f;
    int col0 = colt * 128;
    int tid = threadIdx.x;
    int lane = tid & 31, w = tid >> 5;
    int q = lane >> 2, tg = lane & 3;
    int rowA = col0 + w * 16 + q;
    int rowB = rowA + 8;

    __shared__ float xs[104][72];   // x_t slice [d][b], tf32-rounded

    // A fragments: Wih rows in registers (zero-padded K)
    float aF[13][4];
    #pragma unroll
    for (int kk = 0; kk < 13; ++kk) {
        int k = kk * 8 + tg;
        aF[kk][0] = (k < DIN)     ? d2t(Wih[(size_t)rowA * DIN + k])     : 0.f;
        aF[kk][1] = (k < DIN)     ? d2t(Wih[(size_t)rowB * DIN + k])     : 0.f;
        aF[kk][2] = (k + 4 < DIN) ? d2t(Wih[(size_t)rowA * DIN + k + 4]) : 0.f;
        aF[kk][3] = (k + 4 < DIN) ? d2t(Wih[(size_t)rowB * DIN + k + 4]) : 0.f;
    }
    // zero pad rows 102..103
    for (int i = tid; i < 2 * 64; i += 256) xs[102 + (i >> 6)][i & 63] = 0.f;
    // stage x_t (64 batch x 102 dims), transposed, tf32-rounded
    for (int f = tid; f < 64 * DIN; f += 256) {
        int b = f / DIN, d = f - b * DIN;
        xs[d][b] = d2t(x[((size_t)(bh * 64 + b) * TT + t) * DIN + d]);
    }
    __syncthreads();

    float acc[8][4];
    #pragma unroll
    for (int nt = 0; nt < 8; ++nt)
        #pragma unroll
        for (int j = 0; j < 4; ++j) acc[nt][j] = 0.f;

    #pragma unroll
    for (int kk = 0; kk < 13; ++kk) {
        #pragma unroll
        for (int nt = 0; nt < 8; ++nt) {
            float b0 = xs[kk * 8 + tg][nt * 8 + q];
            float b1 = xs[kk * 8 + tg + 4][nt * 8 + q];
            mma8(acc[nt], aF[kk], b0, b1);
        }
    }

    float bA = bias[rowA], bB = bias[rowB];
    float* gt = g_gates + ((size_t)(dir * TT + t)) * (G4 * BB);
    #pragma unroll
    for (int nt = 0; nt < 8; ++nt) {
        int cb = bh * 64 + nt * 8 + 2 * tg;
        *(float2*)&gt[(size_t)rowA * BB + cb] = make_float2(acc[nt][0] + bA, acc[nt][1] + bA);
        *(float2*)&gt[(size_t)rowB * BB + cb] = make_float2(acc[nt][2] + bB, acc[nt][3] + bB);
    }
}

// ---------------- kernel 2: persistent BiLSTM, tf32 mma ------------------
// 128 CTAs: dir(2) x ug(32) x bh(2); 256 thr. CTA tile: 32 gate rows
// (8 units x 4 gates) x 64 batch. Whh slice in A-fragment registers.
// 4-way split grid barrier (dir, bh), 32 arrivals each.
__global__ void __launch_bounds__(256, 1) k_rnn(
    const float* __restrict__ Whh_f, const float* __restrict__ Whh_b)
{
    int tid  = threadIdx.x;
    int lane = tid & 31, w = tid >> 5;
    int mg = w >> 2;                 // 0..1 : gate pair
    int ng = w & 3;                  // 0..3 : 16-batch group
    int dir = blockIdx.x >> 6;
    int sub = blockIdx.x & 63;
    int ug  = sub >> 1;              // 0..31 unit group
    int bh  = sub & 1;
    int u0  = ug * 8;
    int boff = bh * 64;
    const float* Whh = dir ? Whh_b : Whh_f;

    __shared__ float hs[128][72];    // h k-chunk [k][b64], pad 72: conflict-free
    __shared__ float outs[32][72];   // [gate*8+unit][b64] pre-activations
    __shared__ float csh[8][64];     // persistent cell state [u][b]

    int q  = lane >> 2;              // 0..7
    int tg = lane & 3;               // 0..3
    int rowA = (2 * mg) * 256 + u0 + q;       // gate 2mg, unit q
    int rowB = rowA + 256;                    // gate 2mg+1, unit q
    int n0 = ng * 16;

    // A fragments: 32 rows x 256 k of Whh, tf32-rounded, in registers
    float aF[32][4];
    #pragma unroll
    for (int kk = 0; kk < 32; ++kk) {
        int k = kk * 8 + tg;
        aF[kk][0] = d2t(Whh[(size_t)rowA * HH + k]);
        aF[kk][1] = d2t(Whh[(size_t)rowB * HH + k]);
        aF[kk][2] = d2t(Whh[(size_t)rowA * HH + k + 4]);
        aF[kk][3] = d2t(Whh[(size_t)rowB * HH + k + 4]);
    }
    for (int i = tid; i < 8 * 64; i += 256) ((float*)csh)[i] = 0.f;
    __syncthreads();

    const int HB = HH * BB;
    float* harr = g_h + (size_t)dir * (TT + 1) * HB;
    const float* gbase = g_gates + (size_t)dir * TT * (size_t)(G4 * BB);
    unsigned bidx = (unsigned)(dir * 2 + bh);
    int cb = boff + n0 + 2 * tg;

    // prefetch gates for first step
    float2 gA[2], gB[2];
    {
        int t0 = dir ? (TT - 1) : 0;
        const float* gt = gbase + (size_t)t0 * (G4 * BB);
        #pragma unroll
        for (int nt = 0; nt < 2; ++nt) {
            gA[nt] = *(const float2*)&gt[(size_t)rowA * BB + cb + nt * 8];
            gB[nt] = *(const float2*)&gt[(size_t)rowB * BB + cb + nt * 8];
        }
    }

    int f_row = tid >> 4;            // staging row (0..15 per 256-chunk? no: f>>4)
    int f_c4  = tid & 15;

    for (int s = 0; s < TT; ++s) {
        int t = dir ? (TT - 1 - s) : s;
        const float* hin  = harr + (size_t)(dir ? (t + 1) : t) * HB;
        float*       hout = harr + (size_t)(dir ? t : (t + 1)) * HB;

        float acc[2][4] = {{0.f,0.f,0.f,0.f},{0.f,0.f,0.f,0.f}};
        float4 v[8];

        // ---- chunk 0: k in [0,128) ----
        #pragma unroll
        for (int i = 0; i < 8; ++i) {
            int row = f_row + 16 * i;
            v[i] = *(const float4*)&hin[(size_t)row * BB + boff + f_c4 * 4];
        }
        #pragma unroll
        for (int i = 0; i < 8; ++i)
            *(float4*)&hs[f_row + 16 * i][f_c4 * 4] = v[i];
        __syncthreads();

        // prefetch chunk 1 into regs (overlaps chunk-0 mma)
        #pragma unroll
        for (int i = 0; i < 8; ++i) {
            int row = 128 + f_row + 16 * i;
            v[i] = *(const float4*)&hin[(size_t)row * BB + boff + f_c4 * 4];
        }
        #pragma unroll
        for (int kk = 0; kk < 16; ++kk) {
            #pragma unroll
            for (int nt = 0; nt < 2; ++nt) {
                float b0 = hs[kk * 8 + tg][n0 + nt * 8 + q];
                float b1 = hs[kk * 8 + tg + 4][n0 + nt * 8 + q];
                mma8(acc[nt], aF[kk], b0, b1);
            }
        }
        __syncthreads();

        // ---- chunk 1: k in [128,256) ----
        #pragma unroll
        for (int i = 0; i < 8; ++i)
            *(float4*)&hs[f_row + 16 * i][f_c4 * 4] = v[i];
        __syncthreads();
        #pragma unroll
        for (int kk = 0; kk < 16; ++kk) {
            #pragma unroll
            for (int nt = 0; nt < 2; ++nt) {
                float b0 = hs[kk * 8 + tg][n0 + nt * 8 + q];
                float b1 = hs[kk * 8 + tg + 4][n0 + nt * 8 + q];
                mma8(acc[nt], aF[16 + kk], b0, b1);
            }
        }

        // add input-projection gates (prefetched, exact fp32), stage to outs
        #pragma unroll
        for (int nt = 0; nt < 2; ++nt) {
            acc[nt][0] += gA[nt].x; acc[nt][1] += gA[nt].y;
            acc[nt][2] += gB[nt].x; acc[nt][3] += gB[nt].y;
            *(float2*)&outs[mg * 16 + q][n0 + nt * 8 + 2 * tg] =
                make_float2(acc[nt][0], acc[nt][1]);
            *(float2*)&outs[mg * 16 + q + 8][n0 + nt * 8 + 2 * tg] =
                make_float2(acc[nt][2], acc[nt][3]);
        }
        __syncthreads();

        // LSTM cell epilogue: 8 units x 64 cols
        #pragma unroll
        for (int rep = 0; rep < 2; ++rep) {
            int p = tid + rep * 256;
            int u = p >> 6, cc = p & 63;
            float iv = outs[u][cc];
            float fv = outs[8 + u][cc];
            float gv = outs[16 + u][cc];
            float ov = outs[24 + u][cc];
            float c = sigf(fv) * csh[u][cc] + sigf(iv) * tanhfx(gv);
            csh[u][cc] = c;
            float h = sigf(ov) * tanhfx(c);
            hout[(size_t)(u0 + u) * BB + boff + cc] = d2t(h);  // pre-round tf32
        }

        __threadfence();
        __syncthreads();
        if (tid == 0) atomicAdd(&g_bar4[bidx], 1u);

        // prefetch next step's gates while the barrier drains
        if (s + 1 < TT) {
            int tn = dir ? (t - 1) : (t + 1);
            const float* gt = gbase + (size_t)tn * (G4 * BB);
            #pragma unroll
            for (int nt = 0; nt < 2; ++nt) {
                gA[nt] = *(const float2*)&gt[(size_t)rowA * BB + cb + nt * 8];
                gB[nt] = *(const float2*)&gt[(size_t)rowB * BB + cb + nt * 8];
            }
        }
        if (tid == 0) {
            unsigned target = (unsigned)(s + 1) * 32u;
            while (*((volatile unsigned int*)&g_bar4[bidx]) < target) {}
        }
        __syncthreads();
    }
}

// ---------------- kernel 3: feats + emissions (unchanged) ----------------
__global__ void __launch_bounds__(256) k_feats(
    const float* __restrict__ Wlin, const float* __restrict__ blin,
    const float* __restrict__ Wcls, const float* __restrict__ bcls)
{
    unsigned bx = blockIdx.x;
    int bh = bx & 1;
    int t  = bx >> 1;
    int tid = threadIdx.x;

    __shared__ float smem[9616];
    float* As = smem;               // [32][68]
    float* Ws = smem + 2176;        // [128][36]
    float* Fs = smem;               // phase2: [64][132]
    float* Wc = smem + 8448;        // [9][128]
    float* bc = smem + 9600;        // [9]

    for (int i = tid; i < KK * DLIN; i += 256) Wc[i] = Wcls[i];
    if (tid < KK) bc[tid] = bcls[tid];

    int lane = tid & 31, w = tid >> 5;
    int b0 = (lane & 15) * 4;
    int n0 = w * 16 + (lane >> 4) * 8;
    float acc[8][4];
    #pragma unroll
    for (int n = 0; n < 8; ++n)
        #pragma unroll
        for (int c = 0; c < 4; ++c) acc[n][c] = 0.f;

    const int HB = HH * BB;
    const float* hf = g_h + (size_t)(t + 1) * HB;
    const float* hb = g_h + (size_t)(TT + 1) * HB + (size_t)t * HB;

    for (int kc = 0; kc < 16; ++kc) {
        __syncthreads();
        int kbase = kc * 32;
        for (int i = tid; i < 32 * 64; i += 256) {
            int kr = i >> 6, bb = i & 63;
            int k = kbase + kr;
            float v = (k < HH) ? hf[(size_t)k * BB + bh * 64 + bb]
                               : hb[(size_t)(k - HH) * BB + bh * 64 + bb];
            As[kr * 68 + bb] = v;
        }
        for (int i = tid; i < 128 * 32; i += 256) {
            int n = i >> 5, kr = i & 31;
            Ws[n * 36 + kr] = Wlin[(size_t)n * 512 + kbase + kr];
        }
        __syncthreads();
        #pragma unroll 4
        for (int kr = 0; kr < 32; ++kr) {
            float4 hv = *(const float4*)&As[kr * 68 + b0];
            #pragma unroll
            for (int n = 0; n < 8; ++n) {
                float wv = Ws[(n0 + n) * 36 + kr];
                acc[n][0] += hv.x * wv;
                acc[n][1] += hv.y * wv;
                acc[n][2] += hv.z * wv;
                acc[n][3] += hv.w * wv;
            }
        }
    }
    __syncthreads();

    #pragma unroll
    for (int n = 0; n < 8; ++n) {
        float bl = blin[n0 + n];
        #pragma unroll
        for (int c = 0; c < 4; ++c) {
            float v = acc[n][c] + bl;
            v = (v > 0.f) ? v : expm1f(v);
            Fs[(b0 + c) * 132 + n0 + n] = v;
        }
    }
    __syncthreads();

    for (int p = tid; p < 64 * KK; p += 256) {
        int b = p / KK, k9 = p % KK;
        const float4* fr = (const float4*)&Fs[b * 132];
        const float4* wr = (const float4*)&Wc[k9 * 128];
        float s = 0.f;
        #pragma unroll
        for (int i = 0; i < 32; ++i) {
            float4 f = fr[i], ww = wr[i];
            s += f.x * ww.x + f.y * ww.y + f.z * ww.z + f.w * ww.w;
        }
        int bg = bh * 64 + b;
        g_em[((size_t)bg * TT + t) * KK + k9] = s + bc[k9];
    }
}

// ---------------- kernel 4: CRF NLL (unchanged) --------------------------
__global__ void k_crf(const int* __restrict__ labels,
                      const float* __restrict__ start_t,
                      const float* __restrict__ end_t,
                      const float* __restrict__ trans,
                      float* out)
{
    int b = blockIdx.x;
    int j = threadIdx.x;
    const float* em = g_em + (size_t)b * TT * KK;
    int jj = (j < KK) ? j : 0;
    float tr[KK];
    #pragma unroll
    for (int i = 0; i < KK; ++i) tr[i] = trans[i * KK + jj];

    float alpha = (j < KK) ? (start_t[j] + em[j]) : -1e30f;
    for (int t = 1; t < TT; ++t) {
        float e = (j < KK) ? em[t * KK + j] : 0.f;
        float v[KK];
        float m = -1e30f;
        #pragma unroll
        for (int i = 0; i < KK; ++i) {
            float ai = __shfl_sync(0xffffffffu, alpha, i);
            v[i] = ai + tr[i];
            m = fmaxf(m, v[i]);
        }
        float s = 0.f;
        #pragma unroll
        for (int i = 0; i < KK; ++i) s += expf(v[i] - m);
        float na = m + logf(s) + e;
        alpha = (j < KK) ? na : -1e30f;
    }
    float z = (j < KK) ? (alpha + end_t[j]) : -1e30f;
    float m = z;
    #pragma unroll
    for (int o = 16; o > 0; o >>= 1) m = fmaxf(m, __shfl_xor_sync(0xffffffffu, m, o));
    float s = (j < KK) ? expf(z - m) : 0.f;
    #pragma unroll
    for (int o = 16; o > 0; o >>= 1) s += __shfl_xor_sync(0xffffffffu, s, o);
    float logZ = m + logf(s);

    const int* lb = labels + (size_t)b * TT;
    float part = 0.f;
    for (int t = 1 + j; t < TT; t += 32) {
        int lp = lb[t - 1], lc = lb[t];
        part += trans[lp * KK + lc] + em[t * KK + lc];
    }
    #pragma unroll
    for (int o = 16; o > 0; o >>= 1) part += __shfl_xor_sync(0xffffffffu, part, o);

    if (j == 0) {
        int l0 = lb[0];
        float num = part + start_t[l0] + em[l0] + end_t[lb[TT - 1]];
        atomicAdd(out, logZ - num);
    }
}

// ---------------- host launcher ------------------------------------------
extern "C" void kernel_launch(void* const* d_in, const int* in_sizes, int n_in,
                              void* d_out, int out_size) {
    const float* x      = (const float*)d_in[0];
    const int*   labels = (const int*)d_in[2];
    const float* Wih_f  = (const float*)d_in[4];
    const float* Whh_f  = (const float*)d_in[5];
    const float* b_f    = (const float*)d_in[6];
    const float* Wih_b  = (const float*)d_in[7];
    const float* Whh_b  = (const float*)d_in[8];
    const float* b_b    = (const float*)d_in[9];
    const float* Wlin   = (const float*)d_in[10];
    const float* blin   = (const float*)d_in[11];
    const float* Wcls   = (const float*)d_in[12];
    const float* bcls   = (const float*)d_in[13];
    const float* start_t= (const float*)d_in[14];
    const float* end_t  = (const float*)d_in[15];
    const float* trans  = (const float*)d_in[16];
    float* out = (float*)d_out;

    k_zero<<<64, 256>>>(out);
    k_proj<<<16384, 256>>>(x, Wih_f, b_f, Wih_b, b_b);
    k_rnn<<<128, 256>>>(Whh_f, Whh_b);
    k_feats<<<1024, 256>>>(Wlin, blin, Wcls, bcls);
    k_crf<<<128, 32>>>(labels, start_t, end_t, trans, out);
}

// round 9
// speedup vs baseline: 2.7877x; 1.1273x over previous
#include <cuda_runtime.h>
#include <math.h>

#define TT   512
#define BB   128
#define DIN  102
#define HH   256
#define G4   1024
#define DLIN 128
#define KK   9

// ---------------- device scratch ----------------
// gates layout: [dir][t][col][b]
__device__ float g_gates[(size_t)2 * TT * G4 * BB];
// h layout: [dir][slot][unit][b]; fwd: slot t+1 = h(t), slot0 zeros
//                                 bwd: slot t   = h(t), slot TT zeros
__device__ float g_h[(size_t)2 * (TT + 1) * HH * BB];
__device__ float g_em[(size_t)BB * TT * KK];
__device__ unsigned int g_bar4[4];

__device__ __forceinline__ float d2t(float x) {   // round-to-nearest tf32
    float r;
    asm("cvt.rna.tf32.f32 %0, %1;" : "=f"(r) : "f"(x));
    return r;
}
__device__ __forceinline__ void mma8(float* d, const float* a, float b0, float b1) {
    asm volatile(
        "mma.sync.aligned.m16n8k8.row.col.f32.tf32.tf32.f32 "
        "{%0,%1,%2,%3}, {%4,%5,%6,%7}, {%8,%9}, {%0,%1,%2,%3};\n"
        : "+f"(d[0]), "+f"(d[1]), "+f"(d[2]), "+f"(d[3])
        : "r"(__float_as_uint(a[0])), "r"(__float_as_uint(a[1])),
          "r"(__float_as_uint(a[2])), "r"(__float_as_uint(a[3])),
          "r"(__float_as_uint(b0)), "r"(__float_as_uint(b1)));
}
__device__ __forceinline__ float sigf(float x)  { return 1.f / (1.f + __expf(-x)); }
__device__ __forceinline__ float tanhfx(float x){ return 2.f / (1.f + __expf(-2.f * x)) - 1.f; }

// ---------------- kernel 0 ----------------
__global__ void k_zero(float* out) {
    int idx = blockIdx.x * blockDim.x + threadIdx.x;
    int stride = gridDim.x * blockDim.x;
    if (idx == 0) {
        g_bar4[0] = 0u; g_bar4[1] = 0u; g_bar4[2] = 0u; g_bar4[3] = 0u;
        out[0] = 0.f;
    }
    const int HB = HH * BB;
    float* hf0 = g_h;
    float* hbT = g_h + (size_t)(TT + 1) * HB + (size_t)TT * HB;
    for (int i = idx; i < HB; i += stride) { hf0[i] = 0.f; hbT[i] = 0.f; }
}

// ---------------- kernel 1: gates = x @ Wih^T + b  (tf32 mma) ------------
// grid 16384 = dir(2) x t(512) x colt(8) x bh(2); 256 threads
__global__ void __launch_bounds__(256) k_proj(
    const float* __restrict__ x,
    const float* __restrict__ Wih_f, const float* __restrict__ b_f,
    const float* __restrict__ Wih_b, const float* __restrict__ b_b)
{
    unsigned bx = blockIdx.x;
    int bh   = bx & 1;
    int colt = (bx >> 1) & 7;
    int t    = (bx >> 4) & 511;
    int dir  = bx >> 13;
    const float* Wih  = dir ? Wih_b : Wih_f;
    const float* bias = dir ? b_b : b_f;
    int col0 = colt * 128;
    int tid = threadIdx.x;
    int lane = tid & 31, w = tid >> 5;
    int q = lane >> 2, tg = lane & 3;
    int rowA = col0 + w * 16 + q;
    int rowB = rowA + 8;

    __shared__ float xs[104][72];   // x_t slice [d][b], tf32-rounded

    float aF[13][4];
    #pragma unroll
    for (int kk = 0; kk < 13; ++kk) {
        int k = kk * 8 + tg;
        aF[kk][0] = (k < DIN)     ? d2t(Wih[(size_t)rowA * DIN + k])     : 0.f;
        aF[kk][1] = (k < DIN)     ? d2t(Wih[(size_t)rowB * DIN + k])     : 0.f;
        aF[kk][2] = (k + 4 < DIN) ? d2t(Wih[(size_t)rowA * DIN + k + 4]) : 0.f;
        aF[kk][3] = (k + 4 < DIN) ? d2t(Wih[(size_t)rowB * DIN + k + 4]) : 0.f;
    }
    for (int i = tid; i < 2 * 64; i += 256) xs[102 + (i >> 6)][i & 63] = 0.f;
    for (int f = tid; f < 64 * DIN; f += 256) {
        int b = f / DIN, d = f - b * DIN;
        xs[d][b] = d2t(x[((size_t)(bh * 64 + b) * TT + t) * DIN + d]);
    }
    __syncthreads();

    float acc[8][4];
    #pragma unroll
    for (int nt = 0; nt < 8; ++nt)
        #pragma unroll
        for (int j = 0; j < 4; ++j) acc[nt][j] = 0.f;

    #pragma unroll
    for (int kk = 0; kk < 13; ++kk) {
        #pragma unroll
        for (int nt = 0; nt < 8; ++nt) {
            float b0 = xs[kk * 8 + tg][nt * 8 + q];
            float b1 = xs[kk * 8 + tg + 4][nt * 8 + q];
            mma8(acc[nt], aF[kk], b0, b1);
        }
    }

    float bA = bias[rowA], bB = bias[rowB];
    float* gt = g_gates + ((size_t)(dir * TT + t)) * (G4 * BB);
    #pragma unroll
    for (int nt = 0; nt < 8; ++nt) {
        int cb = bh * 64 + nt * 8 + 2 * tg;
        *(float2*)&gt[(size_t)rowA * BB + cb] = make_float2(acc[nt][0] + bA, acc[nt][1] + bA);
        *(float2*)&gt[(size_t)rowB * BB + cb] = make_float2(acc[nt][2] + bB, acc[nt][3] + bB);
    }
}

// ---------------- kernel 2: persistent BiLSTM, tf32 mma ------------------
// 128 CTAs: dir(2) x ug(32) x bh(2); 256 thr. 32 gate rows x 64 batch per
// CTA. Release-atomic grid barrier (4 groups of 32), no full fences.
__global__ void __launch_bounds__(256, 1) k_rnn(
    const float* __restrict__ Whh_f, const float* __restrict__ Whh_b)
{
    int tid  = threadIdx.x;
    int lane = tid & 31, w = tid >> 5;
    int mg = w >> 2;
    int ng = w & 3;
    int dir = blockIdx.x >> 6;
    int sub = blockIdx.x & 63;
    int ug  = sub >> 1;
    int bh  = sub & 1;
    int u0  = ug * 8;
    int boff = bh * 64;
    const float* Whh = dir ? Whh_b : Whh_f;

    __shared__ float hs[128][72];
    __shared__ float outs[32][72];
    __shared__ float csh[8][64];

    int q  = lane >> 2;
    int tg = lane & 3;
    int rowA = (2 * mg) * 256 + u0 + q;
    int rowB = rowA + 256;
    int n0 = ng * 16;

    float aF[32][4];
    #pragma unroll
    for (int kk = 0; kk < 32; ++kk) {
        int k = kk * 8 + tg;
        aF[kk][0] = d2t(Whh[(size_t)rowA * HH + k]);
        aF[kk][1] = d2t(Whh[(size_t)rowB * HH + k]);
        aF[kk][2] = d2t(Whh[(size_t)rowA * HH + k + 4]);
        aF[kk][3] = d2t(Whh[(size_t)rowB * HH + k + 4]);
    }
    for (int i = tid; i < 8 * 64; i += 256) ((float*)csh)[i] = 0.f;
    __syncthreads();

    const int HB = HH * BB;
    float* harr = g_h + (size_t)dir * (TT + 1) * HB;
    const float* gbase = g_gates + (size_t)dir * TT * (size_t)(G4 * BB);
    unsigned bidx = (unsigned)(dir * 2 + bh);
    unsigned int* barp = &g_bar4[bidx];
    int cb = boff + n0 + 2 * tg;

    float2 gA[2], gB[2];
    {
        int t0 = dir ? (TT - 1) : 0;
        const float* gt = gbase + (size_t)t0 * (G4 * BB);
        #pragma unroll
        for (int nt = 0; nt < 2; ++nt) {
            gA[nt] = *(const float2*)&gt[(size_t)rowA * BB + cb + nt * 8];
            gB[nt] = *(const float2*)&gt[(size_t)rowB * BB + cb + nt * 8];
        }
    }

    int f_row = tid >> 4;
    int f_c4  = tid & 15;

    for (int s = 0; s < TT; ++s) {
        int t = dir ? (TT - 1 - s) : s;
        const float* hin  = harr + (size_t)(dir ? (t + 1) : t) * HB;
        float*       hout = harr + (size_t)(dir ? t : (t + 1)) * HB;

        float acc[2][4] = {{0.f,0.f,0.f,0.f},{0.f,0.f,0.f,0.f}};
        float4 v[8];

        // chunk 0: k in [0,128)
        #pragma unroll
        for (int i = 0; i < 8; ++i) {
            int row = f_row + 16 * i;
            v[i] = *(const float4*)&hin[(size_t)row * BB + boff + f_c4 * 4];
        }
        #pragma unroll
        for (int i = 0; i < 8; ++i)
            *(float4*)&hs[f_row + 16 * i][f_c4 * 4] = v[i];
        __syncthreads();

        #pragma unroll
        for (int i = 0; i < 8; ++i) {
            int row = 128 + f_row + 16 * i;
            v[i] = *(const float4*)&hin[(size_t)row * BB + boff + f_c4 * 4];
        }
        #pragma unroll
        for (int kk = 0; kk < 16; ++kk) {
            #pragma unroll
            for (int nt = 0; nt < 2; ++nt) {
                float b0 = hs[kk * 8 + tg][n0 + nt * 8 + q];
                float b1 = hs[kk * 8 + tg + 4][n0 + nt * 8 + q];
                mma8(acc[nt], aF[kk], b0, b1);
            }
        }
        __syncthreads();

        // chunk 1: k in [128,256)
        #pragma unroll
        for (int i = 0; i < 8; ++i)
            *(float4*)&hs[f_row + 16 * i][f_c4 * 4] = v[i];
        __syncthreads();
        #pragma unroll
        for (int kk = 0; kk < 16; ++kk) {
            #pragma unroll
            for (int nt = 0; nt < 2; ++nt) {
                float b0 = hs[kk * 8 + tg][n0 + nt * 8 + q];
                float b1 = hs[kk * 8 + tg + 4][n0 + nt * 8 + q];
                mma8(acc[nt], aF[16 + kk], b0, b1);
            }
        }

        #pragma unroll
        for (int nt = 0; nt < 2; ++nt) {
            acc[nt][0] += gA[nt].x; acc[nt][1] += gA[nt].y;
            acc[nt][2] += gB[nt].x; acc[nt][3] += gB[nt].y;
            *(float2*)&outs[mg * 16 + q][n0 + nt * 8 + 2 * tg] =
                make_float2(acc[nt][0], acc[nt][1]);
            *(float2*)&outs[mg * 16 + q + 8][n0 + nt * 8 + 2 * tg] =
                make_float2(acc[nt][2], acc[nt][3]);
        }
        __syncthreads();

        #pragma unroll
        for (int rep = 0; rep < 2; ++rep) {
            int p = tid + rep * 256;
            int u = p >> 6, cc = p & 63;
            float iv = outs[u][cc];
            float fv = outs[8 + u][cc];
            float gv = outs[16 + u][cc];
            float ov = outs[24 + u][cc];
            float c = sigf(fv) * csh[u][cc] + sigf(iv) * tanhfx(gv);
            csh[u][cc] = c;
            float h = sigf(ov) * tanhfx(c);
            hout[(size_t)(u0 + u) * BB + boff + cc] = d2t(h);
        }

        // release-arrival: orders this CTA's h stores at gpu scope,
        // no standalone MEMBAR needed.
        __syncthreads();
        if (tid == 0) {
            unsigned one = 1u;
            asm volatile("red.release.gpu.global.add.u32 [%0], %1;"
                         :: "l"(barp), "r"(one) : "memory");
        }

        // prefetch next step's gates while the barrier drains
        if (s + 1 < TT) {
            int tn = dir ? (t - 1) : (t + 1);
            const float* gt = gbase + (size_t)tn * (G4 * BB);
            #pragma unroll
            for (int nt = 0; nt < 2; ++nt) {
                gA[nt] = *(const float2*)&gt[(size_t)rowA * BB + cb + nt * 8];
                gB[nt] = *(const float2*)&gt[(size_t)rowB * BB + cb + nt * 8];
            }
        }
        if (tid == 0) {
            unsigned target = (unsigned)(s + 1) * 32u;
            while (*((volatile unsigned int*)barp) < target) {}
        }
        __syncthreads();
    }
}

// ---------------- kernel 3: feats + emissions (tf32 mma) -----------------
// grid 1024 = t(512) x bh(2); 256 thr. feats[128n][64b] = Wlin @ hcat,
// then ELU, then 9-col classifier.
__global__ void __launch_bounds__(256) k_feats(
    const float* __restrict__ Wlin, const float* __restrict__ blin,
    const float* __restrict__ Wcls, const float* __restrict__ bcls)
{
    unsigned bx = blockIdx.x;
    int bh = bx & 1;
    int t  = bx >> 1;
    int tid = threadIdx.x;
    int lane = tid & 31, w = tid >> 5;
    int q = lane >> 2, tg = lane & 3;

    __shared__ float smem[9616];
    float* As = smem;               // phase1: [32][72]  h chunk  (2304)
    float* Ws = smem + 2304;        // phase1: [128][36] Wlin chunk (4608)
    float* Fs = smem;               // phase2: [64][132] feats (8448)
    float* Wc = smem + 8448;        // [9][128]
    float* bc = smem + 9600;        // [9]

    for (int i = tid; i < KK * DLIN; i += 256) Wc[i] = Wcls[i];
    if (tid < KK) bc[tid] = bcls[tid];

    int n0w = w * 16;
    float acc[8][4];
    #pragma unroll
    for (int nt = 0; nt < 8; ++nt)
        #pragma unroll
        for (int j = 0; j < 4; ++j) acc[nt][j] = 0.f;

    const int HB = HH * BB;
    const float* hf = g_h + (size_t)(t + 1) * HB;
    const float* hb = g_h + (size_t)(TT + 1) * HB + (size_t)t * HB;

    for (int kc = 0; kc < 16; ++kc) {
        __syncthreads();
        int kbase = kc * 32;
        // stage h chunk [32][64] (already tf32-rounded in g_h)
        for (int i = tid; i < 512; i += 256) {
            int kr = i >> 4, c4 = i & 15;
            int k = kbase + kr;
            const float* src = (k < HH) ? &hf[(size_t)k * BB + bh * 64]
                                        : &hb[(size_t)(k - HH) * BB + bh * 64];
            *(float4*)&As[kr * 72 + c4 * 4] = *(const float4*)&src[c4 * 4];
        }
        // stage Wlin chunk [128][32], tf32-rounded
        for (int i = tid; i < 1024; i += 256) {
            int n = i >> 3, c4 = i & 7;
            float4 vv = *(const float4*)&Wlin[(size_t)n * 512 + kbase + c4 * 4];
            vv.x = d2t(vv.x); vv.y = d2t(vv.y); vv.z = d2t(vv.z); vv.w = d2t(vv.w);
            *(float4*)&Ws[n * 36 + c4 * 4] = vv;
        }
        __syncthreads();
        #pragma unroll
        for (int kk = 0; kk < 4; ++kk) {
            float a[4];
            a[0] = Ws[(n0w + q) * 36 + kk * 8 + tg];
            a[1] = Ws[(n0w + q + 8) * 36 + kk * 8 + tg];
            a[2] = Ws[(n0w + q) * 36 + kk * 8 + tg + 4];
            a[3] = Ws[(n0w + q + 8) * 36 + kk * 8 + tg + 4];
            #pragma unroll
            for (int nt = 0; nt < 8; ++nt) {
                float b0 = As[(kk * 8 + tg) * 72 + nt * 8 + q];
                float b1 = As[(kk * 8 + tg + 4) * 72 + nt * 8 + q];
                mma8(acc[nt], a, b0, b1);
            }
        }
    }
    __syncthreads();

    // ELU + store feats Fs[b][n]
    float blA = blin[n0w + q], blB = blin[n0w + q + 8];
    #pragma unroll
    for (int nt = 0; nt < 8; ++nt) {
        int b = nt * 8 + 2 * tg;
        float v0 = acc[nt][0] + blA;
        float v1 = acc[nt][1] + blA;
        float v2 = acc[nt][2] + blB;
        float v3 = acc[nt][3] + blB;
        v0 = (v0 > 0.f) ? v0 : expm1f(v0);
        v1 = (v1 > 0.f) ? v1 : expm1f(v1);
        v2 = (v2 > 0.f) ? v2 : expm1f(v2);
        v3 = (v3 > 0.f) ? v3 : expm1f(v3);
        Fs[b * 132 + n0w + q] = v0;
        Fs[(b + 1) * 132 + n0w + q] = v1;
        Fs[b * 132 + n0w + q + 8] = v2;
        Fs[(b + 1) * 132 + n0w + q + 8] = v3;
    }
    __syncthreads();

    // emissions: 64 b x 9 k
    for (int p = tid; p < 64 * KK; p += 256) {
        int b = p / KK, k9 = p % KK;
        const float4* fr = (const float4*)&Fs[b * 132];
        const float4* wr = (const float4*)&Wc[k9 * 128];
        float s = 0.f;
        #pragma unroll
        for (int i = 0; i < 32; ++i) {
            float4 f = fr[i], ww = wr[i];
            s += f.x * ww.x + f.y * ww.y + f.z * ww.z + f.w * ww.w;
        }
        int bg = bh * 64 + b;
        g_em[((size_t)bg * TT + t) * KK + k9] = s + bc[k9];
    }
}

// ---------------- kernel 4: CRF NLL --------------------------------------
__global__ void k_crf(const int* __restrict__ labels,
                      const float* __restrict__ start_t,
                      const float* __restrict__ end_t,
                      const float* __restrict__ trans,
                      float* out)
{
    int b = blockIdx.x;
    int j = threadIdx.x;
    const float* em = g_em + (size_t)b * TT * KK;
    int jj = (j < KK) ? j : 0;
    float tr[KK];
    #pragma unroll
    for (int i = 0; i < KK; ++i) tr[i] = trans[i * KK + jj];

    float alpha = (j < KK) ? (start_t[j] + em[j]) : -1e30f;
    for (int t = 1; t < TT; ++t) {
        float e = (j < KK) ? em[t * KK + j] : 0.f;
        float v[KK];
        float m = -1e30f;
        #pragma unroll
        for (int i = 0; i < KK; ++i) {
            float ai = __shfl_sync(0xffffffffu, alpha, i);
            v[i] = ai + tr[i];
            m = fmaxf(m, v[i]);
        }
        float s = 0.f;
        #pragma unroll
        for (int i = 0; i < KK; ++i) s += expf(v[i] - m);
        float na = m + logf(s) + e;
        alpha = (j < KK) ? na : -1e30f;
    }
    float z = (j < KK) ? (alpha + end_t[j]) : -1e30f;
    float m = z;
    #pragma unroll
    for (int o = 16; o > 0; o >>= 1) m = fmaxf(m, __shfl_xor_sync(0xffffffffu, m, o));
    float s = (j < KK) ? expf(z - m) : 0.f;
    #pragma unroll
    for (int o = 16; o > 0; o >>= 1) s += __shfl_xor_sync(0xffffffffu, s, o);
    float logZ = m + logf(s);

    const int* lb = labels + (size_t)b * TT;
    float part = 0.f;
    for (int t = 1 + j; t < TT; t += 32) {
        int lp = lb[t - 1], lc = lb[t];
        part += trans[lp * KK + lc] + em[t * KK + lc];
    }
    #pragma unroll
    for (int o = 16; o > 0; o >>= 1) part += __shfl_xor_sync(0xffffffffu, part, o);

    if (j == 0) {
        int l0 = lb[0];
        float num = part + start_t[l0] + em[l0] + end_t[lb[TT - 1]];
        atomicAdd(out, logZ - num);
    }
}

// ---------------- host launcher ------------------------------------------
extern "C" void kernel_launch(void* const* d_in, const int* in_sizes, int n_in,
                              void* d_out, int out_size) {
    const float* x      = (const float*)d_in[0];
    const int*   labels = (const int*)d_in[2];
    const float* Wih_f  = (const float*)d_in[4];
    const float* Whh_f  = (const float*)d_in[5];
    const float* b_f    = (const float*)d_in[6];
    const float* Wih_b  = (const float*)d_in[7];
    const float* Whh_b  = (const float*)d_in[8];
    const float* b_b    = (const float*)d_in[9];
    const float* Wlin   = (const float*)d_in[10];
    const float* blin   = (const float*)d_in[11];
    const float* Wcls   = (const float*)d_in[12];
    const float* bcls   = (const float*)d_in[13];
    const float* start_t= (const float*)d_in[14];
    const float* end_t  = (const float*)d_in[15];
    const float* trans  = (const float*)d_in[16];
    float* out = (float*)d_out;

    k_zero<<<64, 256>>>(out);
    k_proj<<<16384, 256>>>(x, Wih_f, b_f, Wih_b, b_b);
    k_rnn<<<128, 256>>>(Whh_f, Whh_b);
    k_feats<<<1024, 256>>>(Wlin, blin, Wcls, bcls);
    k_crf<<<128, 32>>>(labels, start_t, end_t, trans, out);
}

// round 11
// speedup vs baseline: 3.1530x; 1.1310x over previous
#include <cuda_runtime.h>
#include <cuda_bf16.h>
#include <math.h>

#define TT   512
#define BB   128
#define DIN  102
#define HH   256
#define G4   1024
#define DLIN 128
#define KK   9

// ---------------- device scratch ----------------
// gates layout: [dir][t][col][b]  (fp32)
__device__ float g_gates[(size_t)2 * TT * G4 * BB];
// h layout: bf16 [dir][slot][b][unit] (unit contiguous!)
// fwd: slot t+1 = h(t), slot0 zeros; bwd: slot t = h(t), slot TT zeros
__device__ __nv_bfloat16 g_h16[(size_t)2 * (TT + 1) * BB * HH];
__device__ float g_em[(size_t)BB * TT * KK];
__device__ unsigned int g_bar4[4];

__device__ __forceinline__ float d2t(float x) {   // round-to-nearest tf32
    float r;
    asm("cvt.rna.tf32.f32 %0, %1;" : "=f"(r) : "f"(x));
    return r;
}
__device__ __forceinline__ unsigned pk2(float lo, float hi) {
    __nv_bfloat162 t = __floats2bfloat162_rn(lo, hi);   // x=lo(low16), y=hi
    return *(unsigned*)&t;
}
__device__ __forceinline__ void mma8(float* d, const float* a, float b0, float b1) {
    asm volatile(
        "mma.sync.aligned.m16n8k8.row.col.f32.tf32.tf32.f32 "
        "{%0,%1,%2,%3}, {%4,%5,%6,%7}, {%8,%9}, {%0,%1,%2,%3};\n"
        : "+f"(d[0]), "+f"(d[1]), "+f"(d[2]), "+f"(d[3])
        : "r"(__float_as_uint(a[0])), "r"(__float_as_uint(a[1])),
          "r"(__float_as_uint(a[2])), "r"(__float_as_uint(a[3])),
          "r"(__float_as_uint(b0)), "r"(__float_as_uint(b1)));
}
__device__ __forceinline__ void mma16(float* d, const unsigned* a,
                                      unsigned b0, unsigned b1) {
    asm volatile(
        "mma.sync.aligned.m16n8k16.row.col.f32.bf16.bf16.f32 "
        "{%0,%1,%2,%3}, {%4,%5,%6,%7}, {%8,%9}, {%0,%1,%2,%3};\n"
        : "+f"(d[0]), "+f"(d[1]), "+f"(d[2]), "+f"(d[3])
        : "r"(a[0]), "r"(a[1]), "r"(a[2]), "r"(a[3]),
          "r"(b0), "r"(b1));
}
__device__ __forceinline__ float sigf(float x)  { return 1.f / (1.f + __expf(-x)); }
__device__ __forceinline__ float tanhfx(float x){ return 2.f / (1.f + __expf(-2.f * x)) - 1.f; }

// ---------------- kernel 0 ----------------
__global__ void k_zero(float* out) {
    int idx = blockIdx.x * blockDim.x + threadIdx.x;
    int stride = gridDim.x * blockDim.x;
    if (idx == 0) {
        g_bar4[0] = 0u; g_bar4[1] = 0u; g_bar4[2] = 0u; g_bar4[3] = 0u;
        out[0] = 0.f;
    }
    const int HBW = BB * HH / 2;   // uints per slot
    unsigned* hf0 = (unsigned*)g_h16;                                   // dir0 slot0
    unsigned* hbT = (unsigned*)(g_h16 + (size_t)((TT + 1) + TT) * BB * HH); // dir1 slotTT
    for (int i = idx; i < HBW; i += stride) { hf0[i] = 0u; hbT[i] = 0u; }
}

// ---------------- kernel 1: gates = x @ Wih^T + b  (tf32 mma, unchanged) -
__global__ void __launch_bounds__(256) k_proj(
    const float* __restrict__ x,
    const float* __restrict__ Wih_f, const float* __restrict__ b_f,
    const float* __restrict__ Wih_b, const float* __restrict__ b_b)
{
    unsigned bx = blockIdx.x;
    int bh   = bx & 1;
    int colt = (bx >> 1) & 7;
    int t    = (bx >> 4) & 511;
    int dir  = bx >> 13;
    const float* Wih  = dir ? Wih_b : Wih_f;
    const float* bias = dir ? b_b : b_f;
    int col0 = colt * 128;
    int tid = threadIdx.x;
    int lane = tid & 31, w = tid >> 5;
    int q = lane >> 2, tg = lane & 3;
    int rowA = col0 + w * 16 + q;
    int rowB = rowA + 8;

    __shared__ float xs[104][72];

    float aF[13][4];
    #pragma unroll
    for (int kk = 0; kk < 13; ++kk) {
        int k = kk * 8 + tg;
        aF[kk][0] = (k < DIN)     ? d2t(Wih[(size_t)rowA * DIN + k])     : 0.f;
        aF[kk][1] = (k < DIN)     ? d2t(Wih[(size_t)rowB * DIN + k])     : 0.f;
        aF[kk][2] = (k + 4 < DIN) ? d2t(Wih[(size_t)rowA * DIN + k + 4]) : 0.f;
        aF[kk][3] = (k + 4 < DIN) ? d2t(Wih[(size_t)rowB * DIN + k + 4]) : 0.f;
    }
    for (int i = tid; i < 2 * 64; i += 256) xs[102 + (i >> 6)][i & 63] = 0.f;
    for (int f = tid; f < 64 * DIN; f += 256) {
        int b = f / DIN, d = f - b * DIN;
        xs[d][b] = d2t(x[((size_t)(bh * 64 + b) * TT + t) * DIN + d]);
    }
    __syncthreads();

    float acc[8][4];
    #pragma unroll
    for (int nt = 0; nt < 8; ++nt)
        #pragma unroll
        for (int j = 0; j < 4; ++j) acc[nt][j] = 0.f;

    #pragma unroll
    for (int kk = 0; kk < 13; ++kk) {
        #pragma unroll
        for (int nt = 0; nt < 8; ++nt) {
            float b0 = xs[kk * 8 + tg][nt * 8 + q];
            float b1 = xs[kk * 8 + tg + 4][nt * 8 + q];
            mma8(acc[nt], aF[kk], b0, b1);
        }
    }

    float bA = bias[rowA], bB = bias[rowB];
    float* gt = g_gates + ((size_t)(dir * TT + t)) * (G4 * BB);
    #pragma unroll
    for (int nt = 0; nt < 8; ++nt) {
        int cb = bh * 64 + nt * 8 + 2 * tg;
        *(float2*)&gt[(size_t)rowA * BB + cb] = make_float2(acc[nt][0] + bA, acc[nt][1] + bA);
        *(float2*)&gt[(size_t)rowB * BB + cb] = make_float2(acc[nt][2] + bB, acc[nt][3] + bB);
    }
}

// ---------------- kernel 2: persistent BiLSTM, bf16 m16n8k16 mma ---------
// 128 CTAs: dir(2) x ug(32) x bh(2); 256 thr. 32 gate rows x 64 batch.
__global__ void __launch_bounds__(256, 1) k_rnn(
    const float* __restrict__ Whh_f, const float* __restrict__ Whh_b)
{
    int tid  = threadIdx.x;
    int lane = tid & 31, w = tid >> 5;
    int mg = w >> 2;                  // 0..1: gate pair (i,f)/(g,o)
    int ng = w & 3;                   // 0..3: 16-batch group
    int dir = blockIdx.x >> 6;
    int sub = blockIdx.x & 63;
    int ug  = sub >> 1;
    int bh  = sub & 1;
    int u0  = ug * 8;
    int boff = bh * 64;
    const float* Whh = dir ? Whh_b : Whh_f;

    __shared__ unsigned hsW[64 * 132];        // h tile [b][k] bf16, pitch 132 words
    __shared__ float outs[32][72];            // pre-activation gates
    __shared__ float csh[8][64];              // cell state [u][b]
    __shared__ __nv_bfloat16 hb[64][8];       // h out staging [b][u]

    int q  = lane >> 2;
    int tg = lane & 3;
    int rowA = (2 * mg) * 256 + u0 + q;
    int rowB = rowA + 256;
    int n0 = ng * 16;

    // bf16 A fragments: 32 rows x 256 k of Whh in 64 regs
    unsigned aF[16][4];
    {
        const float* WA = Whh + (size_t)rowA * HH;
        const float* WB = Whh + (size_t)rowB * HH;
        #pragma unroll
        for (int kk = 0; kk < 16; ++kk) {
            int k0 = kk * 16 + 2 * tg;
            float2 a0 = *(const float2*)&WA[k0];
            float2 a1 = *(const float2*)&WB[k0];
            float2 a2 = *(const float2*)&WA[k0 + 8];
            float2 a3 = *(const float2*)&WB[k0 + 8];
            aF[kk][0] = pk2(a0.x, a0.y);
            aF[kk][1] = pk2(a1.x, a1.y);
            aF[kk][2] = pk2(a2.x, a2.y);
            aF[kk][3] = pk2(a3.x, a3.y);
        }
    }
    for (int i = tid; i < 8 * 64; i += 256) ((float*)csh)[i] = 0.f;
    __syncthreads();

    const size_t HB = (size_t)BB * HH;
    __nv_bfloat16* harr = g_h16 + (size_t)dir * (TT + 1) * HB;
    const float* gbase = g_gates + (size_t)dir * TT * (size_t)(G4 * BB);
    unsigned bidx = (unsigned)(dir * 2 + bh);
    unsigned int* barp = &g_bar4[bidx];
    int cb = boff + n0 + 2 * tg;

    float2 gA[2], gB[2];
    {
        int t0 = dir ? (TT - 1) : 0;
        const float* gt = gbase + (size_t)t0 * (G4 * BB);
        #pragma unroll
        for (int nt = 0; nt < 2; ++nt) {
            gA[nt] = *(const float2*)&gt[(size_t)rowA * BB + cb + nt * 8];
            gB[nt] = *(const float2*)&gt[(size_t)rowB * BB + cb + nt * 8];
        }
    }

    int srow = tid >> 5;      // 0..7
    int scol = tid & 31;      // 16B column

    for (int s = 0; s < TT; ++s) {
        int t = dir ? (TT - 1 - s) : s;
        const __nv_bfloat16* hin = harr + (size_t)(dir ? (t + 1) : t) * HB
                                        + (size_t)boff * HH;
        __nv_bfloat16* hout = harr + (size_t)(dir ? t : (t + 1)) * HB;

        // stage h tile [64 b][256 k] bf16 -> smem (coalesced LDG.128)
        uint4 v[8];
        #pragma unroll
        for (int i = 0; i < 8; ++i)
            v[i] = ((const uint4*)(hin + (size_t)(srow + 8 * i) * HH))[scol];
        #pragma unroll
        for (int i = 0; i < 8; ++i)
            *(uint4*)&hsW[(srow + 8 * i) * 132 + scol * 4] = v[i];
        __syncthreads();

        float acc[2][4] = {{0.f,0.f,0.f,0.f},{0.f,0.f,0.f,0.f}};
        #pragma unroll
        for (int kk = 0; kk < 16; ++kk) {
            #pragma unroll
            for (int nt = 0; nt < 2; ++nt) {
                int base = (n0 + nt * 8 + q) * 132 + kk * 8 + tg;
                unsigned b0 = hsW[base];
                unsigned b1 = hsW[base + 4];
                mma16(acc[nt], aF[kk], b0, b1);
            }
        }

        // add input-projection gates (fp32), stage to outs
        #pragma unroll
        for (int nt = 0; nt < 2; ++nt) {
            acc[nt][0] += gA[nt].x; acc[nt][1] += gA[nt].y;
            acc[nt][2] += gB[nt].x; acc[nt][3] += gB[nt].y;
            *(float2*)&outs[mg * 16 + q][n0 + nt * 8 + 2 * tg] =
                make_float2(acc[nt][0], acc[nt][1]);
            *(float2*)&outs[mg * 16 + q + 8][n0 + nt * 8 + 2 * tg] =
                make_float2(acc[nt][2], acc[nt][3]);
        }
        __syncthreads();

        // LSTM cell epilogue: 8 units x 64 cols
        #pragma unroll
        for (int rep = 0; rep < 2; ++rep) {
            int p = tid + rep * 256;
            int u = p >> 6, cc = p & 63;
            float iv = outs[u][cc];
            float fv = outs[8 + u][cc];
            float gv = outs[16 + u][cc];
            float ov = outs[24 + u][cc];
            float c = sigf(fv) * csh[u][cc] + sigf(iv) * tanhfx(gv);
            csh[u][cc] = c;
            float h = sigf(ov) * tanhfx(c);
            hb[cc][u] = __float2bfloat16_rn(h);
        }
        __syncthreads();

        // cooperative h writeback: 64 threads x 16B
        if (tid < 64) {
            uint4 hv = *(uint4*)&hb[tid][0];
            *(uint4*)(hout + (size_t)(boff + tid) * HH + u0) = hv;
        }
        __syncthreads();
        if (tid == 0) {
            unsigned one = 1u;
            asm volatile("red.release.gpu.global.add.u32 [%0], %1;"
                         :: "l"(barp), "r"(one) : "memory");
        }

        // prefetch next step's gates while the barrier drains
        if (s + 1 < TT) {
            int tn = dir ? (t - 1) : (t + 1);
            const float* gt = gbase + (size_t)tn * (G4 * BB);
            #pragma unroll
            for (int nt = 0; nt < 2; ++nt) {
                gA[nt] = *(const float2*)&gt[(size_t)rowA * BB + cb + nt * 8];
                gB[nt] = *(const float2*)&gt[(size_t)rowB * BB + cb + nt * 8];
            }
        }
        if (tid == 0) {
            unsigned target = (unsigned)(s + 1) * 32u;
            while (*((volatile unsigned int*)barp) < target) {}
        }
        __syncthreads();
    }
}

// ---------------- kernel 3: feats + emissions (bf16 mma) -----------------
// grid 1024 = t(512) x bh(2); 256 thr. 8 k-chunks of 64.
__global__ void __launch_bounds__(256) k_feats(
    const float* __restrict__ Wlin, const float* __restrict__ blin,
    const float* __restrict__ Wcls, const float* __restrict__ bcls)
{
    unsigned bx = blockIdx.x;
    int bh = bx & 1;
    int t  = bx >> 1;
    int tid = threadIdx.x;
    int lane = tid & 31, w = tid >> 5;
    int q = lane >> 2, tg = lane & 3;

    __shared__ float smem[9616];
    unsigned* hsW = (unsigned*)smem;          // phase1: [64 b][36w] h chunk
    unsigned* Ws2 = (unsigned*)(smem + 2304); // phase1: [128 n][36w] Wlin chunk
    float* Fs = smem;                         // phase2: [64][132] feats
    float* Wc = smem + 8448;                  // [9][128]
    float* bc = smem + 9600;                  // [9]

    for (int i = tid; i < KK * DLIN; i += 256) Wc[i] = Wcls[i];
    if (tid < KK) bc[tid] = bcls[tid];

    int n0w = w * 16;
    float acc[8][4];
    #pragma unroll
    for (int nt = 0; nt < 8; ++nt)
        #pragma unroll
        for (int j = 0; j < 4; ++j) acc[nt][j] = 0.f;

    const size_t HB = (size_t)BB * HH;
    const __nv_bfloat16* hf = g_h16 + (size_t)(t + 1) * HB + (size_t)(bh * 64) * HH;
    const __nv_bfloat16* hb = g_h16 + (size_t)(TT + 1) * HB + (size_t)t * HB
                                    + (size_t)(bh * 64) * HH;

    int wrow = tid >> 1, wpart = tid & 1;     // Wlin staging
    int hrow0 = tid >> 3, hc8 = tid & 7;      // h staging

    for (int kc = 0; kc < 8; ++kc) {
        __syncthreads();
        int kbase = (kc & 3) * 64;
        const __nv_bfloat16* hsrc = (kc < 4) ? hf : hb;
        // stage h chunk [64 b][64 k] bf16
        #pragma unroll
        for (int i = 0; i < 2; ++i) {
            int row = hrow0 + 32 * i;
            uint4 hv = *(const uint4*)(hsrc + (size_t)row * HH + kbase + hc8 * 8);
            *(uint4*)&hsW[row * 36 + hc8 * 4] = hv;
        }
        // stage Wlin chunk [128 n][64 k], fp32 -> bf16
        int kglob = kc * 64;
        #pragma unroll
        for (int j = 0; j < 8; ++j) {
            float4 vv = *(const float4*)&Wlin[(size_t)wrow * 512 + kglob + wpart * 32 + j * 4];
            unsigned w0 = pk2(vv.x, vv.y);
            unsigned w1 = pk2(vv.z, vv.w);
            *(uint2*)&Ws2[wrow * 36 + wpart * 16 + j * 2] = make_uint2(w0, w1);
        }
        __syncthreads();
        #pragma unroll
        for (int kk = 0; kk < 4; ++kk) {
            unsigned a[4];
            int ab = (n0w + q) * 36 + kk * 8 + tg;
            a[0] = Ws2[ab];
            a[1] = Ws2[ab + 8 * 36];
            a[2] = Ws2[ab + 4];
            a[3] = Ws2[ab + 8 * 36 + 4];
            #pragma unroll
            for (int nt = 0; nt < 8; ++nt) {
                int bbse = (nt * 8 + q) * 36 + kk * 8 + tg;
                mma16(acc[nt], a, hsW[bbse], hsW[bbse + 4]);
            }
        }
    }
    __syncthreads();

    // ELU + store feats Fs[b][n]
    float blA = blin[n0w + q], blB = blin[n0w + q + 8];
    #pragma unroll
    for (int nt = 0; nt < 8; ++nt) {
        int b = nt * 8 + 2 * tg;
        float v0 = acc[nt][0] + blA;
        float v1 = acc[nt][1] + blA;
        float v2 = acc[nt][2] + blB;
        float v3 = acc[nt][3] + blB;
        v0 = (v0 > 0.f) ? v0 : expm1f(v0);
        v1 = (v1 > 0.f) ? v1 : expm1f(v1);
        v2 = (v2 > 0.f) ? v2 : expm1f(v2);
        v3 = (v3 > 0.f) ? v3 : expm1f(v3);
        Fs[b * 132 + n0w + q] = v0;
        Fs[(b + 1) * 132 + n0w + q] = v1;
        Fs[b * 132 + n0w + q + 8] = v2;
        Fs[(b + 1) * 132 + n0w + q + 8] = v3;
    }
    __syncthreads();

    // emissions: 64 b x 9 k
    for (int p = tid; p < 64 * KK; p += 256) {
        int b = p / KK, k9 = p % KK;
        const float4* fr = (const float4*)&Fs[b * 132];
        const float4* wr = (const float4*)&Wc[k9 * 128];
        float s = 0.f;
        #pragma unroll
        for (int i = 0; i < 32; ++i) {
            float4 f = fr[i], ww = wr[i];
            s += f.x * ww.x + f.y * ww.y + f.z * ww.z + f.w * ww.w;
        }
        int bg = bh * 64 + b;
        g_em[((size_t)bg * TT + t) * KK + k9] = s + bc[k9];
    }
}

// ---------------- kernel 4: CRF NLL --------------------------------------
__global__ void k_crf(const int* __restrict__ labels,
                      const float* __restrict__ start_t,
                      const float* __restrict__ end_t,
                      const float* __restrict__ trans,
                      float* out)
{
    int b = blockIdx.x;
    int j = threadIdx.x;
    const float* em = g_em + (size_t)b * TT * KK;
    int jj = (j < KK) ? j : 0;
    float tr[KK];
    #pragma unroll
    for (int i = 0; i < KK; ++i) tr[i] = trans[i * KK + jj];

    float alpha = (j < KK) ? (start_t[j] + em[j]) : -1e30f;
    for (int t = 1; t < TT; ++t) {
        float e = (j < KK) ? em[t * KK + j] : 0.f;
        float v[KK];
        float m = -1e30f;
        #pragma unroll
        for (int i = 0; i < KK; ++i) {
            float ai = __shfl_sync(0xffffffffu, alpha, i);
            v[i] = ai + tr[i];
            m = fmaxf(m, v[i]);
        }
        float s = 0.f;
        #pragma unroll
        for (int i = 0; i < KK; ++i) s += expf(v[i] - m);
        float na = m + logf(s) + e;
        alpha = (j < KK) ? na : -1e30f;
    }
    float z = (j < KK) ? (alpha + end_t[j]) : -1e30f;
    float m = z;
    #pragma unroll
    for (int o = 16; o > 0; o >>= 1) m = fmaxf(m, __shfl_xor_sync(0xffffffffu, m, o));
    float s = (j < KK) ? expf(z - m) : 0.f;
    #pragma unroll
    for (int o = 16; o > 0; o >>= 1) s += __shfl_xor_sync(0xffffffffu, s, o);
    float logZ = m + logf(s);

    const int* lb = labels + (size_t)b * TT;
    float part = 0.f;
    for (int t = 1 + j; t < TT; t += 32) {
        int lp = lb[t - 1], lc = lb[t];
        part += trans[lp * KK + lc] + em[t * KK + lc];
    }
    #pragma unroll
    for (int o = 16; o > 0; o >>= 1) part += __shfl_xor_sync(0xffffffffu, part, o);

    if (j == 0) {
        int l0 = lb[0];
        float num = part + start_t[l0] + em[l0] + end_t[lb[TT - 1]];
        atomicAdd(out, logZ - num);
    }
}

// ---------------- host launcher ------------------------------------------
extern "C" void kernel_launch(void* const* d_in, const int* in_sizes, int n_in,
                              void* d_out, int out_size) {
    const float* x      = (const float*)d_in[0];
    const int*   labels = (const int*)d_in[2];
    const float* Wih_f  = (const float*)d_in[4];
    const float* Whh_f  = (const float*)d_in[5];
    const float* b_f    = (const float*)d_in[6];
    const float* Wih_b  = (const float*)d_in[7];
    const float* Whh_b  = (const float*)d_in[8];
    const float* b_b    = (const float*)d_in[9];
    const float* Wlin   = (const float*)d_in[10];
    const float* blin   = (const float*)d_in[11];
    const float* Wcls   = (const float*)d_in[12];
    const float* bcls   = (const float*)d_in[13];
    const float* start_t= (const float*)d_in[14];
    const float* end_t  = (const float*)d_in[15];
    const float* trans  = (const float*)d_in[16];
    float* out = (float*)d_out;

    k_zero<<<64, 256>>>(out);
    k_proj<<<16384, 256>>>(x, Wih_f, b_f, Wih_b, b_b);
    k_rnn<<<128, 256>>>(Whh_f, Whh_b);
    k_feats<<<1024, 256>>>(Wlin, blin, Wcls, bcls);
    k_crf<<<128, 32>>>(labels, start_t, end_t, trans, out);
}